// round 8
// baseline (speedup 1.0000x reference)
#include <cuda_runtime.h>
#include <cstdint>

// x: [N=64, C=512, H=56, W=56] fp32. 2:4 structured sparsity along C:
// within each group of 4 channels (same n,h,w), zero the 2 smallest-|x|
// entries (ties: lower channel index dropped first, matching jax top_k).
//
// R8 = R7 (session best: plain loads + __stwt write-through stores,
// 32-bit index math, regs=32) with block 256 -> 512. Halves CTA count
// (25088 -> 12544) and wave transitions at identical occupancy
// (4 CTAs x 512 thr = 2048 thr/SM).
//
// Session evidence: R7 = 121.3us @ DRAM 85.4% (best). R1/R3/R4/R6 =
// 121.4-122.0us @ 83.7-85.0%. R2 (MLP=8, occ 40%) and R5 (persistent
// grid-stride) regressed. Op is at the B300 HBM streaming ceiling
// (~6.77 TB/s end-to-end for read+write of 822 MB).

static constexpr int HW4     = (56 * 56) / 4;   // 784 float4 per channel plane
static constexpr int TOTAL_T = 64 * 128 * HW4;  // 6,422,528 (fits int)
static constexpr int BLOCK   = 512;

// keep element i iff at least 2 of the other 3 are "strictly smaller"
// under less(j,i) = (|a_j| < |a_i|) || (|a_j| == |a_i| && j < i).
__device__ __forceinline__ void mask4(float& x0, float& x1, float& x2, float& x3) {
    float a0 = fabsf(x0), a1 = fabsf(x1), a2 = fabsf(x2), a3 = fabsf(x3);
    int r0 = 0, r1 = 0, r2 = 0, r3 = 0;
    if (a0 <= a1) r1++; else r0++;   // less(0,1)=a0<=a1 ; less(1,0)=a1<a0
    if (a0 <= a2) r2++; else r0++;
    if (a0 <= a3) r3++; else r0++;
    if (a1 <= a2) r2++; else r1++;
    if (a1 <= a3) r3++; else r1++;
    if (a2 <= a3) r3++; else r2++;
    x0 = (r0 >= 2) ? x0 : 0.0f;
    x1 = (r1 >= 2) ? x1 : 0.0f;
    x2 = (r2 >= 2) ? x2 : 0.0f;
    x3 = (r3 >= 2) ? x3 : 0.0f;
}

__global__ void __launch_bounds__(BLOCK, 4)
sparsity24_kernel(const float4* __restrict__ x4, float4* __restrict__ o4) {
    int t = blockIdx.x * BLOCK + threadIdx.x;
    if (t >= TOTAL_T) return;

    // decode: t -> (ng, hw4); constant divisor -> mul-shift in SASS
    int hw4 = t % HW4;
    int ng  = t / HW4;
    int base = ng * (4 * HW4) + hw4;   // max 25,690,112 < 2^31

    float4 v0 = x4[base];
    float4 v1 = x4[base + HW4];
    float4 v2 = x4[base + 2 * HW4];
    float4 v3 = x4[base + 3 * HW4];

    mask4(v0.x, v1.x, v2.x, v3.x);
    mask4(v0.y, v1.y, v2.y, v3.y);
    mask4(v0.z, v1.z, v2.z, v3.z);
    mask4(v0.w, v1.w, v2.w, v3.w);

    __stwt(&o4[base],           v0);
    __stwt(&o4[base + HW4],     v1);
    __stwt(&o4[base + 2 * HW4], v2);
    __stwt(&o4[base + 3 * HW4], v3);
}

extern "C" void kernel_launch(void* const* d_in, const int* in_sizes, int n_in,
                              void* d_out, int out_size) {
    const float4* x4 = (const float4*)d_in[0];
    float4* o4 = (float4*)d_out;
    int blocks = (TOTAL_T + BLOCK - 1) / BLOCK;
    sparsity24_kernel<<<blocks, BLOCK>>>(x4, o4);
}

// round 9
// speedup vs baseline: 1.0018x; 1.0018x over previous
#include <cuda_runtime.h>
#include <cstdint>

// x: [N=64, C=512, H=56, W=56] fp32. 2:4 structured sparsity along C:
// within each group of 4 channels (same n,h,w), zero the 2 smallest-|x|
// entries (ties: lower channel index dropped first, matching jax top_k).
//
// R9 = R7 (session best: 121.3us, DRAM 85.4%) with __ldcg loads.
// Data is single-touch: L1 allocation is pure overhead, so .cg (L2-only)
// shortens L1tex occupancy per load. Stores stay __stwt (write-through,
// no L2 write-allocate) — the measured-best store policy.
//
// Session evidence: R7 (plain ld + stwt, blk256) best at 121.3us/85.4%.
// R8 (blk512) neutral-worse. R1/R3/R4/R6 = 121.4-122.0us. R2 (MLP=8)
// and R5 (persistent) regressed. Op sits at the B300 HBM r+w streaming
// ceiling (~6.77 TB/s end-to-end for 822 MB of irreducible traffic).

static constexpr int HW4     = (56 * 56) / 4;   // 784 float4 per channel plane
static constexpr int TOTAL_T = 64 * 128 * HW4;  // 6,422,528 (fits int)

// keep element i iff at least 2 of the other 3 are "strictly smaller"
// under less(j,i) = (|a_j| < |a_i|) || (|a_j| == |a_i| && j < i).
__device__ __forceinline__ void mask4(float& x0, float& x1, float& x2, float& x3) {
    float a0 = fabsf(x0), a1 = fabsf(x1), a2 = fabsf(x2), a3 = fabsf(x3);
    int r0 = 0, r1 = 0, r2 = 0, r3 = 0;
    if (a0 <= a1) r1++; else r0++;   // less(0,1)=a0<=a1 ; less(1,0)=a1<a0
    if (a0 <= a2) r2++; else r0++;
    if (a0 <= a3) r3++; else r0++;
    if (a1 <= a2) r2++; else r1++;
    if (a1 <= a3) r3++; else r1++;
    if (a2 <= a3) r3++; else r2++;
    x0 = (r0 >= 2) ? x0 : 0.0f;
    x1 = (r1 >= 2) ? x1 : 0.0f;
    x2 = (r2 >= 2) ? x2 : 0.0f;
    x3 = (r3 >= 2) ? x3 : 0.0f;
}

__global__ void __launch_bounds__(256, 8)
sparsity24_kernel(const float4* __restrict__ x4, float4* __restrict__ o4) {
    int t = blockIdx.x * 256 + threadIdx.x;
    if (t >= TOTAL_T) return;

    // decode: t -> (ng, hw4); constant divisor -> mul-shift in SASS
    int hw4 = t % HW4;
    int ng  = t / HW4;
    int base = ng * (4 * HW4) + hw4;   // max 25,690,112 < 2^31

    float4 v0 = __ldcg(&x4[base]);
    float4 v1 = __ldcg(&x4[base + HW4]);
    float4 v2 = __ldcg(&x4[base + 2 * HW4]);
    float4 v3 = __ldcg(&x4[base + 3 * HW4]);

    mask4(v0.x, v1.x, v2.x, v3.x);
    mask4(v0.y, v1.y, v2.y, v3.y);
    mask4(v0.z, v1.z, v2.z, v3.z);
    mask4(v0.w, v1.w, v2.w, v3.w);

    __stwt(&o4[base],           v0);
    __stwt(&o4[base + HW4],     v1);
    __stwt(&o4[base + 2 * HW4], v2);
    __stwt(&o4[base + 3 * HW4], v3);
}

extern "C" void kernel_launch(void* const* d_in, const int* in_sizes, int n_in,
                              void* d_out, int out_size) {
    const float4* x4 = (const float4*)d_in[0];
    float4* o4 = (float4*)d_out;
    int blocks = (TOTAL_T + 255) / 256;
    sparsity24_kernel<<<blocks, 256>>>(x4, o4);
}